// round 9
// baseline (speedup 1.0000x reference)
#include <cuda_runtime.h>
#include <cuda_fp16.h>
#include <cstdint>

#define N_USER 100000
#define N_ITEM 200000
#define N_NODE 300000
#define LATDIM 64
#define E_INTER 4000000
#define E_SOC   2000000
#define E_TOT   (E_INTER + E_SOC)
#define N_LAYER 4
#define NBINS   (N_NODE + N_USER)   // inter bins [0,300000), soc bins [300000,400000)

#define NUF ((size_t)N_USER * LATDIM)
#define NNF ((size_t)N_NODE * LATDIM)

// fp16 embeddings: fused16[0]=fp16(concat(uE,iE)); fused16[1..4]/soc16[1..4]
// are written by the consumer SpMM (plain stores, f32 register accumulation).
__device__ __half g_fused16[5][NNF];
__device__ __half g_soc16[4][NUF];
// CSR: edges sorted by destination row. rec = {col, val_f32_bits}.
__device__ uint2 g_csr[E_TOT];
__device__ int   g_P[NBINS];        // counts -> exclusive prefix -> (post-scatter) bin ends
__device__ int   g_bsum[256];

// ---------------------------------------------------------------------------
// Stage 1: zero the bin counters.
// ---------------------------------------------------------------------------
__global__ __launch_bounds__(256) void zerobins_kernel(int* __restrict__ P) {
    int i = blockIdx.x * 256 + threadIdx.x;
    if (i < NBINS) P[i] = 0;
}

// ---------------------------------------------------------------------------
// Stage 2: histogram of destination rows (+ build fused16[0], independent).
// ---------------------------------------------------------------------------
#define H_I 15625            // E_INTER / 256
#define H_S 7813             // ceil(E_SOC / 256)
#define H_B 1024             // fused16[0] build

__global__ __launch_bounds__(256) void hist_kernel(
    int* __restrict__ P,
    const int* __restrict__ ir, const int* __restrict__ sr,
    const float4* __restrict__ uE4, const float4* __restrict__ iE4,
    uint2* __restrict__ h0)
{
    unsigned b = blockIdx.x;
    int tid = threadIdx.x;
    if (b < H_I) {
        int e = (int)b * 256 + tid;
        atomicAdd(P + __ldg(ir + e), 1);
    } else if (b < H_I + H_S) {
        int e = (int)(b - H_I) * 256 + tid;
        if (e < E_SOC) atomicAdd(P + N_NODE + __ldg(sr + e), 1);
    } else {
        const size_t nU4 = NUF / 4, nN4 = NNF / 4;
        size_t stride = (size_t)H_B * 256;
        for (size_t i = (size_t)(b - H_I - H_S) * 256 + tid; i < nN4; i += stride) {
            float4 v = (i < nU4) ? __ldg(uE4 + i) : __ldg(iE4 + (i - nU4));
            __half2 a = __floats2half2_rn(v.x, v.y);
            __half2 c = __floats2half2_rn(v.z, v.w);
            uint2 st;
            st.x = *reinterpret_cast<unsigned*>(&a);
            st.y = *reinterpret_cast<unsigned*>(&c);
            h0[i] = st;
        }
    }
}

// ---------------------------------------------------------------------------
// Stage 3/4/5: exclusive prefix scan of P (block scan -> top scan -> add).
// ---------------------------------------------------------------------------
#define SCAN_ELEMS 2048      // per block: 256 threads x 8
#define SCAN_BLOCKS ((NBINS + SCAN_ELEMS - 1) / SCAN_ELEMS)   // 196

__global__ __launch_bounds__(256) void scan_blocks_kernel(
    int* __restrict__ P, int* __restrict__ bsum)
{
    __shared__ int sh[256];
    int b = blockIdx.x, t = threadIdx.x;
    int base = b * SCAN_ELEMS + t * 8;
    int v[8], s = 0;
    #pragma unroll
    for (int i = 0; i < 8; i++) {
        v[i] = (base + i < NBINS) ? P[base + i] : 0;
        s += v[i];
    }
    sh[t] = s;
    __syncthreads();
    #pragma unroll
    for (int off = 1; off < 256; off <<= 1) {
        int x = sh[t];
        int y = (t >= off) ? sh[t - off] : 0;
        __syncthreads();
        sh[t] = x + y;
        __syncthreads();
    }
    int run = sh[t] - s;   // exclusive prefix of this thread's chunk
    #pragma unroll
    for (int i = 0; i < 8; i++) {
        int nv = run;
        run += v[i];
        if (base + i < NBINS) P[base + i] = nv;
    }
    if (t == 255) bsum[b] = run;
}

__global__ __launch_bounds__(256) void scan_top_kernel(int* __restrict__ bsum) {
    __shared__ int sh[256];
    int t = threadIdx.x;
    int v = (t < SCAN_BLOCKS) ? bsum[t] : 0;
    sh[t] = v;
    __syncthreads();
    #pragma unroll
    for (int off = 1; off < 256; off <<= 1) {
        int x = sh[t];
        int y = (t >= off) ? sh[t - off] : 0;
        __syncthreads();
        sh[t] = x + y;
        __syncthreads();
    }
    if (t < SCAN_BLOCKS) bsum[t] = sh[t] - v;   // exclusive
}

__global__ __launch_bounds__(256) void addoff_kernel(
    int* __restrict__ P, const int* __restrict__ bsum)
{
    int i = blockIdx.x * 256 + threadIdx.x;
    if (i < NBINS) P[i] += __ldg(bsum + i / SCAN_ELEMS);
}

// ---------------------------------------------------------------------------
// Stage 6: scatter edges into CSR slots (fetch-add turns P into bin ends).
// ---------------------------------------------------------------------------
__global__ __launch_bounds__(256) void scatter_kernel(
    int* __restrict__ P, uint2* __restrict__ csr,
    const int* __restrict__ ir, const int* __restrict__ ic, const float* __restrict__ iv,
    const int* __restrict__ sr, const int* __restrict__ sc, const float* __restrict__ sv)
{
    unsigned b = blockIdx.x;
    int tid = threadIdx.x;
    uint2 rec;
    int bin;
    if (b < H_I) {
        int e = (int)b * 256 + tid;
        bin = __ldg(ir + e);
        rec.x = (unsigned)__ldg(ic + e);
        rec.y = __float_as_uint(__ldg(iv + e));
    } else {
        int e = (int)(b - H_I) * 256 + tid;
        if (e >= E_SOC) return;
        bin = N_NODE + __ldg(sr + e);
        rec.x = (unsigned)__ldg(sc + e);
        rec.y = __float_as_uint(__ldg(sv + e));
    }
    int slot = atomicAdd(P + bin, 1);
    csr[slot] = rec;
}

// ---------------------------------------------------------------------------
// Consumer SpMM (dual): one warp per output row, grid-stride over all
// NBINS rows (inter rows then soc rows). Batch-load 32 edge records,
// shfl-broadcast, gather 4 B/lane (128 B/edge), accumulate f32 in registers,
// one fp16 128 B store per row. No atomics, no zero-init.
// ---------------------------------------------------------------------------
__global__ __launch_bounds__(256) void spmm_csr_kernel(
    const uint2* __restrict__ csr, const int* __restrict__ P,
    const __half* __restrict__ xI, __half* __restrict__ oI,
    const __half* __restrict__ xS, __half* __restrict__ oS)
{
    int warp = (blockIdx.x * blockDim.x + threadIdx.x) >> 5;
    int lane = threadIdx.x & 31;
    int nw = (gridDim.x * blockDim.x) >> 5;

    for (int row = warp; row < NBINS; row += nw) {
        int start = (row == 0) ? 0 : __ldg(P + row - 1);
        int end = __ldg(P + row);
        const __half* X;
        __half* O;
        int drow;
        if (row < N_NODE) { X = xI; O = oI; drow = row; }
        else              { X = xS; O = oS; drow = row - N_NODE; }

        float2 acc = make_float2(0.f, 0.f);
        for (int e0 = start; e0 < end; e0 += 32) {
            uint2 rec = (e0 + lane < end) ? __ldg(csr + e0 + lane) : make_uint2(0u, 0u);
            int nb = min(32, end - e0);
            int j = 0;
            for (; j + 4 <= nb; j += 4) {
                int c0 = __shfl_sync(0xffffffffu, rec.x, j);
                int c1 = __shfl_sync(0xffffffffu, rec.x, j + 1);
                int c2 = __shfl_sync(0xffffffffu, rec.x, j + 2);
                int c3 = __shfl_sync(0xffffffffu, rec.x, j + 3);
                float v0 = __uint_as_float(__shfl_sync(0xffffffffu, rec.y, j));
                float v1 = __uint_as_float(__shfl_sync(0xffffffffu, rec.y, j + 1));
                float v2 = __uint_as_float(__shfl_sync(0xffffffffu, rec.y, j + 2));
                float v3 = __uint_as_float(__shfl_sync(0xffffffffu, rec.y, j + 3));
                unsigned h0 = __ldg(reinterpret_cast<const unsigned*>(X + (size_t)c0 * LATDIM) + lane);
                unsigned h1 = __ldg(reinterpret_cast<const unsigned*>(X + (size_t)c1 * LATDIM) + lane);
                unsigned h2 = __ldg(reinterpret_cast<const unsigned*>(X + (size_t)c2 * LATDIM) + lane);
                unsigned h3 = __ldg(reinterpret_cast<const unsigned*>(X + (size_t)c3 * LATDIM) + lane);
                float2 f0 = __half22float2(*reinterpret_cast<__half2*>(&h0));
                float2 f1 = __half22float2(*reinterpret_cast<__half2*>(&h1));
                float2 f2 = __half22float2(*reinterpret_cast<__half2*>(&h2));
                float2 f3 = __half22float2(*reinterpret_cast<__half2*>(&h3));
                acc.x = fmaf(v0, f0.x, acc.x); acc.y = fmaf(v0, f0.y, acc.y);
                acc.x = fmaf(v1, f1.x, acc.x); acc.y = fmaf(v1, f1.y, acc.y);
                acc.x = fmaf(v2, f2.x, acc.x); acc.y = fmaf(v2, f2.y, acc.y);
                acc.x = fmaf(v3, f3.x, acc.x); acc.y = fmaf(v3, f3.y, acc.y);
            }
            for (; j < nb; j++) {
                int c = __shfl_sync(0xffffffffu, rec.x, j);
                float v = __uint_as_float(__shfl_sync(0xffffffffu, rec.y, j));
                unsigned h = __ldg(reinterpret_cast<const unsigned*>(X + (size_t)c * LATDIM) + lane);
                float2 f = __half22float2(*reinterpret_cast<__half2*>(&h));
                acc.x = fmaf(v, f.x, acc.x);
                acc.y = fmaf(v, f.y, acc.y);
            }
        }
        *reinterpret_cast<__half2*>(O + (size_t)drow * LATDIM + lane * 2) =
            __floats2half2_rn(acc.x, acc.y);
    }
}

// ---------------------------------------------------------------------------
// Gate: one warp per user row, fp16 in/out (math in f32).
// ---------------------------------------------------------------------------
#define GATE_B 12500         // N_USER * 32 / 256

__global__ __launch_bounds__(256) void gate_kernel(
    const __half* __restrict__ Z,   // soc16[k]
    __half* __restrict__ F,         // fused16[k], user rows in/out
    const float* __restrict__ Wg, const float* __restrict__ bg)
{
    int w = (blockIdx.x * blockDim.x + threadIdx.x) >> 5;
    int lane = threadIdx.x & 31;
    if (w >= N_USER) return;
    size_t base = (size_t)w * LATDIM + lane * 2;
    float2 z = __half22float2(*reinterpret_cast<const __half2*>(Z + base));
    float2 h = __half22float2(*reinterpret_cast<const __half2*>(F + base));
    int d = lane * 2;
    float a0 = z.x * __ldg(Wg + d)       + z.y * __ldg(Wg + d + 1)
             + h.x * __ldg(Wg + 64 + d)  + h.y * __ldg(Wg + 64 + d + 1);
    float a1 = z.x * __ldg(Wg + 128 + d) + z.y * __ldg(Wg + 128 + d + 1)
             + h.x * __ldg(Wg + 192 + d) + h.y * __ldg(Wg + 192 + d + 1);
    #pragma unroll
    for (int o = 16; o; o >>= 1) {
        a0 += __shfl_xor_sync(0xffffffffu, a0, o);
        a1 += __shfl_xor_sync(0xffffffffu, a1, o);
    }
    a0 += __ldg(bg);
    a1 += __ldg(bg + 1);
    a0 = a0 > 0.f ? a0 : 0.01f * a0;
    a1 = a1 > 0.f ? a1 : 0.01f * a1;
    float mx = fmaxf(a0, a1);
    float e0 = __expf(a0 - mx), e1 = __expf(a1 - mx);
    float inv = 1.f / (e0 + e1);
    float m0 = e0 * inv, m1 = e1 * inv;
    *reinterpret_cast<__half2*>(F + base) =
        __floats2half2_rn(z.x * m0 + h.x * m1, z.y * m0 + h.y * m1);
}

// ---------------------------------------------------------------------------
// Final combine: one warp per node; layer-0 rows from uE/iE (f32).
// ---------------------------------------------------------------------------
__global__ __launch_bounds__(256) void final_kernel(
    const float* __restrict__ uE, const float* __restrict__ iE,
    const __half* __restrict__ F1, const __half* __restrict__ F2,
    const __half* __restrict__ F3, const __half* __restrict__ F4,
    const float* __restrict__ WL1, const float* __restrict__ bL1,
    const float* __restrict__ WL2, const float* __restrict__ bL2,
    float* __restrict__ out)
{
    int w = (blockIdx.x * blockDim.x + threadIdx.x) >> 5;
    int lane = threadIdx.x & 31;
    if (w >= N_NODE) return;
    bool isU = (w < N_USER);
    const float* W = isU ? WL1 : WL2;
    const float* b = isU ? bL1 : bL2;
    size_t base = (size_t)w * LATDIM + lane * 2;
    float2 f[5];
    f[0] = isU ? *reinterpret_cast<const float2*>(uE + base)
               : *reinterpret_cast<const float2*>(iE + (base - NUF));
    f[1] = __half22float2(*reinterpret_cast<const __half2*>(F1 + base));
    f[2] = __half22float2(*reinterpret_cast<const __half2*>(F2 + base));
    f[3] = __half22float2(*reinterpret_cast<const __half2*>(F3 + base));
    f[4] = __half22float2(*reinterpret_cast<const __half2*>(F4 + base));
    float lg[5];
    int d = lane * 2;
    #pragma unroll
    for (int j = 0; j < 5; j++) {
        float acc = 0.f;
        #pragma unroll
        for (int k = 0; k < 5; k++) {
            const float* wr = W + j * 320 + k * 64 + d;
            acc += f[k].x * __ldg(wr) + f[k].y * __ldg(wr + 1);
        }
        lg[j] = acc;
    }
    #pragma unroll
    for (int o = 16; o; o >>= 1) {
        #pragma unroll
        for (int j = 0; j < 5; j++) lg[j] += __shfl_xor_sync(0xffffffffu, lg[j], o);
    }
    float mx = -1e30f;
    #pragma unroll
    for (int j = 0; j < 5; j++) {
        lg[j] += __ldg(b + j);
        lg[j] = lg[j] > 0.f ? lg[j] : 0.01f * lg[j];
        mx = fmaxf(mx, lg[j]);
    }
    float s = 0.f;
    #pragma unroll
    for (int j = 0; j < 5; j++) { lg[j] = __expf(lg[j] - mx); s += lg[j]; }
    float inv = 1.f / s;
    float2 o2 = make_float2(0.f, 0.f);
    #pragma unroll
    for (int j = 0; j < 5; j++) {
        float wk = lg[j] * inv;
        o2.x += wk * f[j].x;
        o2.y += wk * f[j].y;
    }
    *reinterpret_cast<float2*>(out + base) = o2;
}

// ---------------------------------------------------------------------------
// host
// ---------------------------------------------------------------------------
static inline int cdiv_ll(long long a, int b) { return (int)((a + b - 1) / b); }

extern "C" void kernel_launch(void* const* d_in, const int* in_sizes, int n_in,
                              void* d_out, int out_size)
{
    const float* uE  = (const float*)d_in[0];
    const float* iE  = (const float*)d_in[1];
    const float* Wg  = (const float*)d_in[2];   // (5,2,128)
    const float* bg  = (const float*)d_in[3];   // (5,2)
    const float* WL1 = (const float*)d_in[4];   // (5,320)
    const float* bL1 = (const float*)d_in[5];
    const float* WL2 = (const float*)d_in[6];
    const float* bL2 = (const float*)d_in[7];
    const int*   ir  = (const int*)d_in[8];
    const int*   ic  = (const int*)d_in[9];
    const float* iv  = (const float*)d_in[10];
    const int*   sr  = (const int*)d_in[11];
    const int*   sc  = (const int*)d_in[12];
    const float* sv  = (const float*)d_in[13];
    float* out = (float*)d_out;

    void *pf16, *ps16, *pcsr, *pP, *pbs;
    cudaGetSymbolAddress(&pf16, g_fused16);
    cudaGetSymbolAddress(&ps16, g_soc16);
    cudaGetSymbolAddress(&pcsr, g_csr);
    cudaGetSymbolAddress(&pP, g_P);
    cudaGetSymbolAddress(&pbs, g_bsum);

    __half* fused16[5];
    for (int k = 0; k <= 4; k++) fused16[k] = (__half*)pf16 + (size_t)k * NNF;
    __half* soc16[5];
    soc16[0] = nullptr;
    for (int l = 1; l <= 4; l++) soc16[l] = (__half*)ps16 + (size_t)(l - 1) * NUF;
    __half* socsrc[4];
    socsrc[0] = fused16[0];   // layer-0 soc source = fused16[0] user rows
    for (int l = 1; l < 4; l++) socsrc[l] = soc16[l];
    uint2* csr = (uint2*)pcsr;
    int* P = (int*)pP;
    int* bsum = (int*)pbs;

    // --- CSR build (one-time) + fused16[0] ---
    zerobins_kernel<<<cdiv_ll(NBINS, 256), 256>>>(P);
    hist_kernel<<<H_I + H_S + H_B, 256>>>(
        P, ir, sr, (const float4*)uE, (const float4*)iE, (uint2*)fused16[0]);
    scan_blocks_kernel<<<SCAN_BLOCKS, 256>>>(P, bsum);
    scan_top_kernel<<<1, 256>>>(bsum);
    addoff_kernel<<<cdiv_ll(NBINS, 256), 256>>>(P, bsum);
    scatter_kernel<<<H_I + H_S, 256>>>(P, csr, ir, ic, iv, sr, sc, sv);

    // --- layers ---
    const int SPMM_BLOCKS = 2368;   // 148 SMs * 16, grid-stride over 400k rows
    for (int k = 0; k < N_LAYER; k++) {
        spmm_csr_kernel<<<SPMM_BLOCKS, 256>>>(
            csr, P,
            fused16[k], fused16[k + 1],
            socsrc[k], soc16[k + 1]);
        gate_kernel<<<GATE_B, 256>>>(
            soc16[k + 1], fused16[k + 1],
            Wg + (size_t)(k + 1) * 256, bg + (size_t)(k + 1) * 2);
    }

    final_kernel<<<cdiv_ll((long long)N_NODE * 32, 256), 256>>>(
        uE, iE, fused16[1], fused16[2], fused16[3], fused16[4],
        WL1, bL1, WL2, bL2, out);
}

// round 10
// speedup vs baseline: 1.0745x; 1.0745x over previous
#include <cuda_runtime.h>
#include <cuda_fp16.h>
#include <cstdint>

#define N_USER 100000
#define N_ITEM 200000
#define N_NODE 300000
#define LATDIM 64
#define E_INTER 4000000
#define E_SOC   2000000
#define E_TOT   (E_INTER + E_SOC)
#define N_LAYER 4
#define NBINS   (N_NODE + N_USER)   // inter bins [0,300000), soc bins [300000,400000)

#define NUF ((size_t)N_USER * LATDIM)
#define NNF ((size_t)N_NODE * LATDIM)

// fp16 embeddings: fused16[0]=fp16(concat(uE,iE)); fused16[1..4]/soc16[1..4]
// written by the consumer SpMM (plain stores, f32 register accumulation).
__device__ __half g_fused16[5][NNF];
__device__ __half g_soc16[4][NUF];
// CSR: edges sorted by destination row. rec = {col, val_f32_bits}.
__device__ uint2 g_csr[E_TOT];
__device__ int   g_P[NBINS];        // counts -> exclusive prefix -> bin ends
__device__ int   g_bsum[256];

// ---------------------------------------------------------------------------
// Stage 1: zero bin counters.
// ---------------------------------------------------------------------------
__global__ __launch_bounds__(256) void zerobins_kernel(int* __restrict__ P) {
    int i = blockIdx.x * 256 + threadIdx.x;
    if (i < NBINS) P[i] = 0;
}

// ---------------------------------------------------------------------------
// Stage 2: histogram of destination rows (+ build fused16[0], independent).
// ---------------------------------------------------------------------------
#define H_I 15625            // E_INTER / 256
#define H_S 7813             // ceil(E_SOC / 256)
#define H_B 1024             // fused16[0] build

__global__ __launch_bounds__(256) void hist_kernel(
    int* __restrict__ P,
    const int* __restrict__ ir, const int* __restrict__ sr,
    const float4* __restrict__ uE4, const float4* __restrict__ iE4,
    uint2* __restrict__ h0)
{
    unsigned b = blockIdx.x;
    int tid = threadIdx.x;
    if (b < H_I) {
        int e = (int)b * 256 + tid;
        atomicAdd(P + __ldg(ir + e), 1);
    } else if (b < H_I + H_S) {
        int e = (int)(b - H_I) * 256 + tid;
        if (e < E_SOC) atomicAdd(P + N_NODE + __ldg(sr + e), 1);
    } else {
        const size_t nU4 = NUF / 4, nN4 = NNF / 4;
        size_t stride = (size_t)H_B * 256;
        for (size_t i = (size_t)(b - H_I - H_S) * 256 + tid; i < nN4; i += stride) {
            float4 v = (i < nU4) ? __ldg(uE4 + i) : __ldg(iE4 + (i - nU4));
            __half2 a = __floats2half2_rn(v.x, v.y);
            __half2 c = __floats2half2_rn(v.z, v.w);
            uint2 st;
            st.x = *reinterpret_cast<unsigned*>(&a);
            st.y = *reinterpret_cast<unsigned*>(&c);
            h0[i] = st;
        }
    }
}

// ---------------------------------------------------------------------------
// Stage 3/4/5: exclusive prefix scan of P.
// ---------------------------------------------------------------------------
#define SCAN_ELEMS 2048
#define SCAN_BLOCKS ((NBINS + SCAN_ELEMS - 1) / SCAN_ELEMS)   // 196

__global__ __launch_bounds__(256) void scan_blocks_kernel(
    int* __restrict__ P, int* __restrict__ bsum)
{
    __shared__ int sh[256];
    int b = blockIdx.x, t = threadIdx.x;
    int base = b * SCAN_ELEMS + t * 8;
    int v[8], s = 0;
    #pragma unroll
    for (int i = 0; i < 8; i++) {
        v[i] = (base + i < NBINS) ? P[base + i] : 0;
        s += v[i];
    }
    sh[t] = s;
    __syncthreads();
    #pragma unroll
    for (int off = 1; off < 256; off <<= 1) {
        int x = sh[t];
        int y = (t >= off) ? sh[t - off] : 0;
        __syncthreads();
        sh[t] = x + y;
        __syncthreads();
    }
    int run = sh[t] - s;
    #pragma unroll
    for (int i = 0; i < 8; i++) {
        int nv = run;
        run += v[i];
        if (base + i < NBINS) P[base + i] = nv;
    }
    if (t == 255) bsum[b] = run;
}

__global__ __launch_bounds__(256) void scan_top_kernel(int* __restrict__ bsum) {
    __shared__ int sh[256];
    int t = threadIdx.x;
    int v = (t < SCAN_BLOCKS) ? bsum[t] : 0;
    sh[t] = v;
    __syncthreads();
    #pragma unroll
    for (int off = 1; off < 256; off <<= 1) {
        int x = sh[t];
        int y = (t >= off) ? sh[t - off] : 0;
        __syncthreads();
        sh[t] = x + y;
        __syncthreads();
    }
    if (t < SCAN_BLOCKS) bsum[t] = sh[t] - v;
}

__global__ __launch_bounds__(256) void addoff_kernel(
    int* __restrict__ P, const int* __restrict__ bsum)
{
    int i = blockIdx.x * 256 + threadIdx.x;
    if (i < NBINS) P[i] += __ldg(bsum + i / SCAN_ELEMS);
}

// ---------------------------------------------------------------------------
// Stage 6: scatter edges into CSR slots (fetch-add turns P into bin ends).
// ---------------------------------------------------------------------------
__global__ __launch_bounds__(256) void scatter_kernel(
    int* __restrict__ P, uint2* __restrict__ csr,
    const int* __restrict__ ir, const int* __restrict__ ic, const float* __restrict__ iv,
    const int* __restrict__ sr, const int* __restrict__ sc, const float* __restrict__ sv)
{
    unsigned b = blockIdx.x;
    int tid = threadIdx.x;
    uint2 rec;
    int bin;
    if (b < H_I) {
        int e = (int)b * 256 + tid;
        bin = __ldg(ir + e);
        rec.x = (unsigned)__ldg(ic + e);
        rec.y = __float_as_uint(__ldg(iv + e));
    } else {
        int e = (int)(b - H_I) * 256 + tid;
        if (e >= E_SOC) return;
        bin = N_NODE + __ldg(sr + e);
        rec.x = (unsigned)__ldg(sc + e);
        rec.y = __float_as_uint(__ldg(sv + e));
    }
    int slot = atomicAdd(P + bin, 1);
    csr[slot] = rec;
}

// ---------------------------------------------------------------------------
// Consumer SpMM: 16-lane group per output row (2 rows/warp). Lane owns 4
// halves (uint2 = 8 B); gather = 128 B/edge = 1 L1 wavefront. Edge batch
// width 16 matches mean degree. Half-warp masks for shfl (halves diverge).
// f32 register accumulation, one 128 B fp16 store per row. No atomics.
// ---------------------------------------------------------------------------
__global__ __launch_bounds__(256) void spmm_csr_kernel(
    const uint2* __restrict__ csr, const int* __restrict__ P,
    const __half* __restrict__ xI, __half* __restrict__ oI,
    const __half* __restrict__ xS, __half* __restrict__ oS)
{
    int t = blockIdx.x * 256 + threadIdx.x;
    int row = t >> 4;
    int lane = t & 15;
    if (row >= NBINS) return;
    unsigned mask = 0xFFFFu << (threadIdx.x & 16);

    int start = (row == 0) ? 0 : __ldg(P + row - 1);
    int end = __ldg(P + row);
    const __half* X;
    __half* O;
    int drow;
    if (row < N_NODE) { X = xI; O = oI; drow = row; }
    else              { X = xS; O = oS; drow = row - N_NODE; }

    float4 acc = make_float4(0.f, 0.f, 0.f, 0.f);
    for (int e0 = start; e0 < end; e0 += 16) {
        uint2 rec = (e0 + lane < end) ? __ldg(csr + e0 + lane) : make_uint2(0u, 0u);
        int nb = min(16, end - e0);
        int j = 0;
        for (; j + 4 <= nb; j += 4) {
            int c0 = __shfl_sync(mask, (int)rec.x, j, 16);
            int c1 = __shfl_sync(mask, (int)rec.x, j + 1, 16);
            int c2 = __shfl_sync(mask, (int)rec.x, j + 2, 16);
            int c3 = __shfl_sync(mask, (int)rec.x, j + 3, 16);
            float v0 = __uint_as_float(__shfl_sync(mask, rec.y, j, 16));
            float v1 = __uint_as_float(__shfl_sync(mask, rec.y, j + 1, 16));
            float v2 = __uint_as_float(__shfl_sync(mask, rec.y, j + 2, 16));
            float v3 = __uint_as_float(__shfl_sync(mask, rec.y, j + 3, 16));
            uint2 h0 = __ldg(reinterpret_cast<const uint2*>(X + (size_t)c0 * LATDIM) + lane);
            uint2 h1 = __ldg(reinterpret_cast<const uint2*>(X + (size_t)c1 * LATDIM) + lane);
            uint2 h2 = __ldg(reinterpret_cast<const uint2*>(X + (size_t)c2 * LATDIM) + lane);
            uint2 h3 = __ldg(reinterpret_cast<const uint2*>(X + (size_t)c3 * LATDIM) + lane);
            float2 a0 = __half22float2(*reinterpret_cast<__half2*>(&h0.x));
            float2 b0 = __half22float2(*reinterpret_cast<__half2*>(&h0.y));
            float2 a1 = __half22float2(*reinterpret_cast<__half2*>(&h1.x));
            float2 b1 = __half22float2(*reinterpret_cast<__half2*>(&h1.y));
            float2 a2 = __half22float2(*reinterpret_cast<__half2*>(&h2.x));
            float2 b2 = __half22float2(*reinterpret_cast<__half2*>(&h2.y));
            float2 a3 = __half22float2(*reinterpret_cast<__half2*>(&h3.x));
            float2 b3 = __half22float2(*reinterpret_cast<__half2*>(&h3.y));
            acc.x = fmaf(v0, a0.x, acc.x); acc.y = fmaf(v0, a0.y, acc.y);
            acc.z = fmaf(v0, b0.x, acc.z); acc.w = fmaf(v0, b0.y, acc.w);
            acc.x = fmaf(v1, a1.x, acc.x); acc.y = fmaf(v1, a1.y, acc.y);
            acc.z = fmaf(v1, b1.x, acc.z); acc.w = fmaf(v1, b1.y, acc.w);
            acc.x = fmaf(v2, a2.x, acc.x); acc.y = fmaf(v2, a2.y, acc.y);
            acc.z = fmaf(v2, b2.x, acc.z); acc.w = fmaf(v2, b2.y, acc.w);
            acc.x = fmaf(v3, a3.x, acc.x); acc.y = fmaf(v3, a3.y, acc.y);
            acc.z = fmaf(v3, b3.x, acc.z); acc.w = fmaf(v3, b3.y, acc.w);
        }
        for (; j < nb; j++) {
            int c = __shfl_sync(mask, (int)rec.x, j, 16);
            float v = __uint_as_float(__shfl_sync(mask, rec.y, j, 16));
            uint2 h = __ldg(reinterpret_cast<const uint2*>(X + (size_t)c * LATDIM) + lane);
            float2 a = __half22float2(*reinterpret_cast<__half2*>(&h.x));
            float2 bb = __half22float2(*reinterpret_cast<__half2*>(&h.y));
            acc.x = fmaf(v, a.x, acc.x); acc.y = fmaf(v, a.y, acc.y);
            acc.z = fmaf(v, bb.x, acc.z); acc.w = fmaf(v, bb.y, acc.w);
        }
    }
    __half2 lo = __floats2half2_rn(acc.x, acc.y);
    __half2 hi = __floats2half2_rn(acc.z, acc.w);
    uint2 st;
    st.x = *reinterpret_cast<unsigned*>(&lo);
    st.y = *reinterpret_cast<unsigned*>(&hi);
    *(reinterpret_cast<uint2*>(O + (size_t)drow * LATDIM) + lane) = st;
}

// ---------------------------------------------------------------------------
// Gate: one warp per user row, fp16 in/out (math in f32).
// ---------------------------------------------------------------------------
#define GATE_B 12500         // N_USER * 32 / 256

__global__ __launch_bounds__(256) void gate_kernel(
    const __half* __restrict__ Z,
    __half* __restrict__ F,
    const float* __restrict__ Wg, const float* __restrict__ bg)
{
    int w = (blockIdx.x * blockDim.x + threadIdx.x) >> 5;
    int lane = threadIdx.x & 31;
    if (w >= N_USER) return;
    size_t base = (size_t)w * LATDIM + lane * 2;
    float2 z = __half22float2(*reinterpret_cast<const __half2*>(Z + base));
    float2 h = __half22float2(*reinterpret_cast<const __half2*>(F + base));
    int d = lane * 2;
    float a0 = z.x * __ldg(Wg + d)       + z.y * __ldg(Wg + d + 1)
             + h.x * __ldg(Wg + 64 + d)  + h.y * __ldg(Wg + 64 + d + 1);
    float a1 = z.x * __ldg(Wg + 128 + d) + z.y * __ldg(Wg + 128 + d + 1)
             + h.x * __ldg(Wg + 192 + d) + h.y * __ldg(Wg + 192 + d + 1);
    #pragma unroll
    for (int o = 16; o; o >>= 1) {
        a0 += __shfl_xor_sync(0xffffffffu, a0, o);
        a1 += __shfl_xor_sync(0xffffffffu, a1, o);
    }
    a0 += __ldg(bg);
    a1 += __ldg(bg + 1);
    a0 = a0 > 0.f ? a0 : 0.01f * a0;
    a1 = a1 > 0.f ? a1 : 0.01f * a1;
    float mx = fmaxf(a0, a1);
    float e0 = __expf(a0 - mx), e1 = __expf(a1 - mx);
    float inv = 1.f / (e0 + e1);
    float m0 = e0 * inv, m1 = e1 * inv;
    *reinterpret_cast<__half2*>(F + base) =
        __floats2half2_rn(z.x * m0 + h.x * m1, z.y * m0 + h.y * m1);
}

// ---------------------------------------------------------------------------
// Final combine: one warp per node; layer-0 rows from uE/iE (f32).
// ---------------------------------------------------------------------------
__global__ __launch_bounds__(256) void final_kernel(
    const float* __restrict__ uE, const float* __restrict__ iE,
    const __half* __restrict__ F1, const __half* __restrict__ F2,
    const __half* __restrict__ F3, const __half* __restrict__ F4,
    const float* __restrict__ WL1, const float* __restrict__ bL1,
    const float* __restrict__ WL2, const float* __restrict__ bL2,
    float* __restrict__ out)
{
    int w = (blockIdx.x * blockDim.x + threadIdx.x) >> 5;
    int lane = threadIdx.x & 31;
    if (w >= N_NODE) return;
    bool isU = (w < N_USER);
    const float* W = isU ? WL1 : WL2;
    const float* b = isU ? bL1 : bL2;
    size_t base = (size_t)w * LATDIM + lane * 2;
    float2 f[5];
    f[0] = isU ? *reinterpret_cast<const float2*>(uE + base)
               : *reinterpret_cast<const float2*>(iE + (base - NUF));
    f[1] = __half22float2(*reinterpret_cast<const __half2*>(F1 + base));
    f[2] = __half22float2(*reinterpret_cast<const __half2*>(F2 + base));
    f[3] = __half22float2(*reinterpret_cast<const __half2*>(F3 + base));
    f[4] = __half22float2(*reinterpret_cast<const __half2*>(F4 + base));
    float lg[5];
    int d = lane * 2;
    #pragma unroll
    for (int j = 0; j < 5; j++) {
        float acc = 0.f;
        #pragma unroll
        for (int k = 0; k < 5; k++) {
            const float* wr = W + j * 320 + k * 64 + d;
            acc += f[k].x * __ldg(wr) + f[k].y * __ldg(wr + 1);
        }
        lg[j] = acc;
    }
    #pragma unroll
    for (int o = 16; o; o >>= 1) {
        #pragma unroll
        for (int j = 0; j < 5; j++) lg[j] += __shfl_xor_sync(0xffffffffu, lg[j], o);
    }
    float mx = -1e30f;
    #pragma unroll
    for (int j = 0; j < 5; j++) {
        lg[j] += __ldg(b + j);
        lg[j] = lg[j] > 0.f ? lg[j] : 0.01f * lg[j];
        mx = fmaxf(mx, lg[j]);
    }
    float s = 0.f;
    #pragma unroll
    for (int j = 0; j < 5; j++) { lg[j] = __expf(lg[j] - mx); s += lg[j]; }
    float inv = 1.f / s;
    float2 o2 = make_float2(0.f, 0.f);
    #pragma unroll
    for (int j = 0; j < 5; j++) {
        float wk = lg[j] * inv;
        o2.x += wk * f[j].x;
        o2.y += wk * f[j].y;
    }
    *reinterpret_cast<float2*>(out + base) = o2;
}

// ---------------------------------------------------------------------------
// host
// ---------------------------------------------------------------------------
static inline int cdiv_ll(long long a, int b) { return (int)((a + b - 1) / b); }

extern "C" void kernel_launch(void* const* d_in, const int* in_sizes, int n_in,
                              void* d_out, int out_size)
{
    const float* uE  = (const float*)d_in[0];
    const float* iE  = (const float*)d_in[1];
    const float* Wg  = (const float*)d_in[2];
    const float* bg  = (const float*)d_in[3];
    const float* WL1 = (const float*)d_in[4];
    const float* bL1 = (const float*)d_in[5];
    const float* WL2 = (const float*)d_in[6];
    const float* bL2 = (const float*)d_in[7];
    const int*   ir  = (const int*)d_in[8];
    const int*   ic  = (const int*)d_in[9];
    const float* iv  = (const float*)d_in[10];
    const int*   sr  = (const int*)d_in[11];
    const int*   sc  = (const int*)d_in[12];
    const float* sv  = (const float*)d_in[13];
    float* out = (float*)d_out;

    void *pf16, *ps16, *pcsr, *pP, *pbs;
    cudaGetSymbolAddress(&pf16, g_fused16);
    cudaGetSymbolAddress(&ps16, g_soc16);
    cudaGetSymbolAddress(&pcsr, g_csr);
    cudaGetSymbolAddress(&pP, g_P);
    cudaGetSymbolAddress(&pbs, g_bsum);

    __half* fused16[5];
    for (int k = 0; k <= 4; k++) fused16[k] = (__half*)pf16 + (size_t)k * NNF;
    __half* soc16[5];
    soc16[0] = nullptr;
    for (int l = 1; l <= 4; l++) soc16[l] = (__half*)ps16 + (size_t)(l - 1) * NUF;
    __half* socsrc[4];
    socsrc[0] = fused16[0];
    for (int l = 1; l < 4; l++) socsrc[l] = soc16[l];
    uint2* csr = (uint2*)pcsr;
    int* P = (int*)pP;
    int* bsum = (int*)pbs;

    // --- CSR build (per call) + fused16[0] ---
    zerobins_kernel<<<cdiv_ll(NBINS, 256), 256>>>(P);
    hist_kernel<<<H_I + H_S + H_B, 256>>>(
        P, ir, sr, (const float4*)uE, (const float4*)iE, (uint2*)fused16[0]);
    scan_blocks_kernel<<<SCAN_BLOCKS, 256>>>(P, bsum);
    scan_top_kernel<<<1, 256>>>(bsum);
    addoff_kernel<<<cdiv_ll(NBINS, 256), 256>>>(P, bsum);
    scatter_kernel<<<H_I + H_S, 256>>>(P, csr, ir, ic, iv, sr, sc, sv);

    // --- layers ---
    const int SPMM_BLOCKS = cdiv_ll((long long)NBINS * 16, 256);  // 25000
    for (int k = 0; k < N_LAYER; k++) {
        spmm_csr_kernel<<<SPMM_BLOCKS, 256>>>(
            csr, P,
            fused16[k], fused16[k + 1],
            socsrc[k], soc16[k + 1]);
        gate_kernel<<<GATE_B, 256>>>(
            soc16[k + 1], fused16[k + 1],
            Wg + (size_t)(k + 1) * 256, bg + (size_t)(k + 1) * 2);
    }

    final_kernel<<<cdiv_ll((long long)N_NODE * 32, 256), 256>>>(
        uE, iE, fused16[1], fused16[2], fused16[3], fused16[4],
        WL1, bL1, WL2, bL2, out);
}

// round 11
// speedup vs baseline: 1.1019x; 1.0255x over previous
#include <cuda_runtime.h>
#include <cuda_fp16.h>
#include <cstdint>

#define N_USER 100000
#define N_ITEM 200000
#define N_NODE 300000
#define LATDIM 64
#define E_INTER 4000000
#define E_SOC   2000000
#define E_TOT   (E_INTER + E_SOC)
#define N_LAYER 4
#define NBINS   (N_NODE + N_USER)   // inter bins [0,300000), soc bins [300000,400000)

#define NUF ((size_t)N_USER * LATDIM)
#define NNF ((size_t)N_NODE * LATDIM)

// fp16 embeddings: fused16[0]=fp16(concat(uE,iE)); fused16[1..4] gated outputs;
// soc16[1..3] raw soc accumulations (soc16[4] never materialized — its only
// consumer, gate4, runs register-resident in the SpMM epilogue).
__device__ __half g_fused16[5][NNF];
__device__ __half g_soc16[3][NUF];
// CSR: edges sorted by destination bin. rec = {col, val_f32_bits}.
__device__ uint2 g_csr[E_TOT];
__device__ int   g_P[NBINS];        // counts -> exclusive prefix -> bin ends
__device__ int   g_bsum[256];

// ---------------------------------------------------------------------------
// Stage 1: zero bin counters.
// ---------------------------------------------------------------------------
__global__ __launch_bounds__(256) void zerobins_kernel(int* __restrict__ P) {
    int i = blockIdx.x * 256 + threadIdx.x;
    if (i < NBINS) P[i] = 0;
}

// ---------------------------------------------------------------------------
// Stage 2: histogram of destination bins (+ build fused16[0], independent).
// ---------------------------------------------------------------------------
#define H_I 15625            // E_INTER / 256
#define H_S 7813             // ceil(E_SOC / 256)
#define H_B 1024             // fused16[0] build

__global__ __launch_bounds__(256) void hist_kernel(
    int* __restrict__ P,
    const int* __restrict__ ir, const int* __restrict__ sr,
    const float4* __restrict__ uE4, const float4* __restrict__ iE4,
    uint2* __restrict__ h0)
{
    unsigned b = blockIdx.x;
    int tid = threadIdx.x;
    if (b < H_I) {
        int e = (int)b * 256 + tid;
        atomicAdd(P + __ldg(ir + e), 1);
    } else if (b < H_I + H_S) {
        int e = (int)(b - H_I) * 256 + tid;
        if (e < E_SOC) atomicAdd(P + N_NODE + __ldg(sr + e), 1);
    } else {
        const size_t nU4 = NUF / 4, nN4 = NNF / 4;
        size_t stride = (size_t)H_B * 256;
        for (size_t i = (size_t)(b - H_I - H_S) * 256 + tid; i < nN4; i += stride) {
            float4 v = (i < nU4) ? __ldg(uE4 + i) : __ldg(iE4 + (i - nU4));
            __half2 a = __floats2half2_rn(v.x, v.y);
            __half2 c = __floats2half2_rn(v.z, v.w);
            uint2 st;
            st.x = *reinterpret_cast<unsigned*>(&a);
            st.y = *reinterpret_cast<unsigned*>(&c);
            h0[i] = st;
        }
    }
}

// ---------------------------------------------------------------------------
// Stage 3: per-block scan. Stage 4: addoff (re-derives the 196-entry top
// scan in shared per block — one launch cheaper than a separate top kernel).
// ---------------------------------------------------------------------------
#define SCAN_ELEMS 2048
#define SCAN_BLOCKS ((NBINS + SCAN_ELEMS - 1) / SCAN_ELEMS)   // 196

__global__ __launch_bounds__(256) void scan_blocks_kernel(
    int* __restrict__ P, int* __restrict__ bsum)
{
    __shared__ int sh[256];
    int b = blockIdx.x, t = threadIdx.x;
    int base = b * SCAN_ELEMS + t * 8;
    int v[8], s = 0;
    #pragma unroll
    for (int i = 0; i < 8; i++) {
        v[i] = (base + i < NBINS) ? P[base + i] : 0;
        s += v[i];
    }
    sh[t] = s;
    __syncthreads();
    #pragma unroll
    for (int off = 1; off < 256; off <<= 1) {
        int x = sh[t];
        int y = (t >= off) ? sh[t - off] : 0;
        __syncthreads();
        sh[t] = x + y;
        __syncthreads();
    }
    int run = sh[t] - s;
    #pragma unroll
    for (int i = 0; i < 8; i++) {
        int nv = run;
        run += v[i];
        if (base + i < NBINS) P[base + i] = nv;
    }
    if (t == 255) bsum[b] = run;
}

__global__ __launch_bounds__(256) void addoff_kernel(
    int* __restrict__ P, const int* __restrict__ bsum)
{
    __shared__ int sh[256];
    int t = threadIdx.x;
    int v = (t < SCAN_BLOCKS) ? __ldg(bsum + t) : 0;
    sh[t] = v;
    __syncthreads();
    #pragma unroll
    for (int off = 1; off < 256; off <<= 1) {
        int x = sh[t];
        int y = (t >= off) ? sh[t - off] : 0;
        __syncthreads();
        sh[t] = x + y;
        __syncthreads();
    }
    sh[t] = sh[t] - v;   // exclusive
    __syncthreads();
    int i = blockIdx.x * 256 + t;
    if (i < NBINS) P[i] += sh[i / SCAN_ELEMS];
}

// ---------------------------------------------------------------------------
// Stage 5: scatter edges into CSR slots (fetch-add turns P into bin ends).
// ---------------------------------------------------------------------------
__global__ __launch_bounds__(256) void scatter_kernel(
    int* __restrict__ P, uint2* __restrict__ csr,
    const int* __restrict__ ir, const int* __restrict__ ic, const float* __restrict__ iv,
    const int* __restrict__ sr, const int* __restrict__ sc, const float* __restrict__ sv)
{
    unsigned b = blockIdx.x;
    int tid = threadIdx.x;
    uint2 rec;
    int bin;
    if (b < H_I) {
        int e = (int)b * 256 + tid;
        bin = __ldg(ir + e);
        rec.x = (unsigned)__ldg(ic + e);
        rec.y = __float_as_uint(__ldg(iv + e));
    } else {
        int e = (int)(b - H_I) * 256 + tid;
        if (e >= E_SOC) return;
        bin = N_NODE + __ldg(sr + e);
        rec.x = (unsigned)__ldg(sc + e);
        rec.y = __float_as_uint(__ldg(sv + e));
    }
    int slot = atomicAdd(P + bin, 1);
    csr[slot] = rec;
}

// ---------------------------------------------------------------------------
// Row accumulation: 16-lane group, lane owns 4 halves (uint2 = 8 B);
// gather = 128 B/edge = 1 L1 wavefront; f32 register accumulation.
// ---------------------------------------------------------------------------
__device__ __forceinline__ float4 row_accum(
    const uint2* __restrict__ csr, const int* __restrict__ P,
    int bin, const __half* __restrict__ X, int lane, unsigned mask)
{
    int start = (bin == 0) ? 0 : __ldg(P + bin - 1);
    int end = __ldg(P + bin);
    float4 acc = make_float4(0.f, 0.f, 0.f, 0.f);
    for (int e0 = start; e0 < end; e0 += 16) {
        uint2 rec = (e0 + lane < end) ? __ldg(csr + e0 + lane) : make_uint2(0u, 0u);
        int nb = min(16, end - e0);
        int j = 0;
        for (; j + 4 <= nb; j += 4) {
            int c0 = __shfl_sync(mask, (int)rec.x, j, 16);
            int c1 = __shfl_sync(mask, (int)rec.x, j + 1, 16);
            int c2 = __shfl_sync(mask, (int)rec.x, j + 2, 16);
            int c3 = __shfl_sync(mask, (int)rec.x, j + 3, 16);
            float v0 = __uint_as_float(__shfl_sync(mask, rec.y, j, 16));
            float v1 = __uint_as_float(__shfl_sync(mask, rec.y, j + 1, 16));
            float v2 = __uint_as_float(__shfl_sync(mask, rec.y, j + 2, 16));
            float v3 = __uint_as_float(__shfl_sync(mask, rec.y, j + 3, 16));
            uint2 h0 = __ldg(reinterpret_cast<const uint2*>(X + (size_t)c0 * LATDIM) + lane);
            uint2 h1 = __ldg(reinterpret_cast<const uint2*>(X + (size_t)c1 * LATDIM) + lane);
            uint2 h2 = __ldg(reinterpret_cast<const uint2*>(X + (size_t)c2 * LATDIM) + lane);
            uint2 h3 = __ldg(reinterpret_cast<const uint2*>(X + (size_t)c3 * LATDIM) + lane);
            float2 a0 = __half22float2(*reinterpret_cast<__half2*>(&h0.x));
            float2 b0 = __half22float2(*reinterpret_cast<__half2*>(&h0.y));
            float2 a1 = __half22float2(*reinterpret_cast<__half2*>(&h1.x));
            float2 b1 = __half22float2(*reinterpret_cast<__half2*>(&h1.y));
            float2 a2 = __half22float2(*reinterpret_cast<__half2*>(&h2.x));
            float2 b2 = __half22float2(*reinterpret_cast<__half2*>(&h2.y));
            float2 a3 = __half22float2(*reinterpret_cast<__half2*>(&h3.x));
            float2 b3 = __half22float2(*reinterpret_cast<__half2*>(&h3.y));
            acc.x = fmaf(v0, a0.x, acc.x); acc.y = fmaf(v0, a0.y, acc.y);
            acc.z = fmaf(v0, b0.x, acc.z); acc.w = fmaf(v0, b0.y, acc.w);
            acc.x = fmaf(v1, a1.x, acc.x); acc.y = fmaf(v1, a1.y, acc.y);
            acc.z = fmaf(v1, b1.x, acc.z); acc.w = fmaf(v1, b1.y, acc.w);
            acc.x = fmaf(v2, a2.x, acc.x); acc.y = fmaf(v2, a2.y, acc.y);
            acc.z = fmaf(v2, b2.x, acc.z); acc.w = fmaf(v2, b2.y, acc.w);
            acc.x = fmaf(v3, a3.x, acc.x); acc.y = fmaf(v3, a3.y, acc.y);
            acc.z = fmaf(v3, b3.x, acc.z); acc.w = fmaf(v3, b3.y, acc.w);
        }
        for (; j < nb; j++) {
            int c = __shfl_sync(mask, (int)rec.x, j, 16);
            float v = __uint_as_float(__shfl_sync(mask, rec.y, j, 16));
            uint2 h = __ldg(reinterpret_cast<const uint2*>(X + (size_t)c * LATDIM) + lane);
            float2 a = __half22float2(*reinterpret_cast<__half2*>(&h.x));
            float2 bb = __half22float2(*reinterpret_cast<__half2*>(&h.y));
            acc.x = fmaf(v, a.x, acc.x); acc.y = fmaf(v, a.y, acc.y);
            acc.z = fmaf(v, bb.x, acc.z); acc.w = fmaf(v, bb.y, acc.w);
        }
    }
    return acc;
}

__device__ __forceinline__ void store_h4(__half* O, size_t row, int lane, float4 v) {
    __half2 lo = __floats2half2_rn(v.x, v.y);
    __half2 hi = __floats2half2_rn(v.z, v.w);
    uint2 st;
    st.x = *reinterpret_cast<unsigned*>(&lo);
    st.y = *reinterpret_cast<unsigned*>(&hi);
    *(reinterpret_cast<uint2*>(O + row * LATDIM) + lane) = st;
}

// ---------------------------------------------------------------------------
// Fused SpMM + gate: 16-lane group per node row. User rows compute BOTH
// inter and soc accumulations, then apply the next layer's gate in registers
// (f32-exact inputs) and store gated fused16 + raw soc16. Item rows store
// the inter accumulation. soc16 store skipped on the last layer.
// ---------------------------------------------------------------------------
__global__ __launch_bounds__(256) void spmm_gate_kernel(
    const uint2* __restrict__ csr, const int* __restrict__ P,
    const __half* __restrict__ xI,   // fused16[k] (all nodes)
    const __half* __restrict__ xS,   // soc source layer k (user rows)
    __half* __restrict__ oF,         // fused16[k+1]
    __half* __restrict__ oS,         // soc16[k+1] or null (last layer)
    const float* __restrict__ Wg,    // (2,128) gate k+1
    const float* __restrict__ bg)    // (2,)
{
    int t = blockIdx.x * 256 + threadIdx.x;
    int row = t >> 4;
    int lane = t & 15;
    if (row >= N_NODE) return;
    unsigned mask = 0xFFFFu << (threadIdx.x & 16);

    float4 accI = row_accum(csr, P, row, xI, lane, mask);

    if (row < N_USER) {
        float4 accS = row_accum(csr, P, N_NODE + row, xS, lane, mask);
        // gate: a_j = [accS, accI] . Wg[j], reduce over 16 lanes
        int d = lane * 4;
        float a0 = accS.x * __ldg(Wg + d)        + accS.y * __ldg(Wg + d + 1)
                 + accS.z * __ldg(Wg + d + 2)    + accS.w * __ldg(Wg + d + 3)
                 + accI.x * __ldg(Wg + 64 + d)   + accI.y * __ldg(Wg + 64 + d + 1)
                 + accI.z * __ldg(Wg + 64 + d + 2) + accI.w * __ldg(Wg + 64 + d + 3);
        float a1 = accS.x * __ldg(Wg + 128 + d)  + accS.y * __ldg(Wg + 128 + d + 1)
                 + accS.z * __ldg(Wg + 128 + d + 2) + accS.w * __ldg(Wg + 128 + d + 3)
                 + accI.x * __ldg(Wg + 192 + d)  + accI.y * __ldg(Wg + 192 + d + 1)
                 + accI.z * __ldg(Wg + 192 + d + 2) + accI.w * __ldg(Wg + 192 + d + 3);
        #pragma unroll
        for (int o = 8; o; o >>= 1) {
            a0 += __shfl_xor_sync(mask, a0, o, 16);
            a1 += __shfl_xor_sync(mask, a1, o, 16);
        }
        a0 += __ldg(bg);
        a1 += __ldg(bg + 1);
        a0 = a0 > 0.f ? a0 : 0.01f * a0;
        a1 = a1 > 0.f ? a1 : 0.01f * a1;
        float mx = fmaxf(a0, a1);
        float e0 = __expf(a0 - mx), e1 = __expf(a1 - mx);
        float inv = 1.f / (e0 + e1);
        float m0 = e0 * inv, m1 = e1 * inv;
        float4 g;
        g.x = accS.x * m0 + accI.x * m1;
        g.y = accS.y * m0 + accI.y * m1;
        g.z = accS.z * m0 + accI.z * m1;
        g.w = accS.w * m0 + accI.w * m1;
        store_h4(oF, (size_t)row, lane, g);
        if (oS) store_h4(oS, (size_t)row, lane, accS);
    } else {
        store_h4(oF, (size_t)row, lane, accI);
    }
}

// ---------------------------------------------------------------------------
// Final combine: one warp per node; layer-0 rows from uE/iE (f32).
// ---------------------------------------------------------------------------
__global__ __launch_bounds__(256) void final_kernel(
    const float* __restrict__ uE, const float* __restrict__ iE,
    const __half* __restrict__ F1, const __half* __restrict__ F2,
    const __half* __restrict__ F3, const __half* __restrict__ F4,
    const float* __restrict__ WL1, const float* __restrict__ bL1,
    const float* __restrict__ WL2, const float* __restrict__ bL2,
    float* __restrict__ out)
{
    int w = (blockIdx.x * blockDim.x + threadIdx.x) >> 5;
    int lane = threadIdx.x & 31;
    if (w >= N_NODE) return;
    bool isU = (w < N_USER);
    const float* W = isU ? WL1 : WL2;
    const float* b = isU ? bL1 : bL2;
    size_t base = (size_t)w * LATDIM + lane * 2;
    float2 f[5];
    f[0] = isU ? *reinterpret_cast<const float2*>(uE + base)
               : *reinterpret_cast<const float2*>(iE + (base - NUF));
    f[1] = __half22float2(*reinterpret_cast<const __half2*>(F1 + base));
    f[2] = __half22float2(*reinterpret_cast<const __half2*>(F2 + base));
    f[3] = __half22float2(*reinterpret_cast<const __half2*>(F3 + base));
    f[4] = __half22float2(*reinterpret_cast<const __half2*>(F4 + base));
    float lg[5];
    int d = lane * 2;
    #pragma unroll
    for (int j = 0; j < 5; j++) {
        float acc = 0.f;
        #pragma unroll
        for (int k = 0; k < 5; k++) {
            const float* wr = W + j * 320 + k * 64 + d;
            acc += f[k].x * __ldg(wr) + f[k].y * __ldg(wr + 1);
        }
        lg[j] = acc;
    }
    #pragma unroll
    for (int o = 16; o; o >>= 1) {
        #pragma unroll
        for (int j = 0; j < 5; j++) lg[j] += __shfl_xor_sync(0xffffffffu, lg[j], o);
    }
    float mx = -1e30f;
    #pragma unroll
    for (int j = 0; j < 5; j++) {
        lg[j] += __ldg(b + j);
        lg[j] = lg[j] > 0.f ? lg[j] : 0.01f * lg[j];
        mx = fmaxf(mx, lg[j]);
    }
    float s = 0.f;
    #pragma unroll
    for (int j = 0; j < 5; j++) { lg[j] = __expf(lg[j] - mx); s += lg[j]; }
    float inv = 1.f / s;
    float2 o2 = make_float2(0.f, 0.f);
    #pragma unroll
    for (int j = 0; j < 5; j++) {
        float wk = lg[j] * inv;
        o2.x += wk * f[j].x;
        o2.y += wk * f[j].y;
    }
    *reinterpret_cast<float2*>(out + base) = o2;
}

// ---------------------------------------------------------------------------
// host
// ---------------------------------------------------------------------------
static inline int cdiv_ll(long long a, int b) { return (int)((a + b - 1) / b); }

extern "C" void kernel_launch(void* const* d_in, const int* in_sizes, int n_in,
                              void* d_out, int out_size)
{
    const float* uE  = (const float*)d_in[0];
    const float* iE  = (const float*)d_in[1];
    const float* Wg  = (const float*)d_in[2];
    const float* bg  = (const float*)d_in[3];
    const float* WL1 = (const float*)d_in[4];
    const float* bL1 = (const float*)d_in[5];
    const float* WL2 = (const float*)d_in[6];
    const float* bL2 = (const float*)d_in[7];
    const int*   ir  = (const int*)d_in[8];
    const int*   ic  = (const int*)d_in[9];
    const float* iv  = (const float*)d_in[10];
    const int*   sr  = (const int*)d_in[11];
    const int*   sc  = (const int*)d_in[12];
    const float* sv  = (const float*)d_in[13];
    float* out = (float*)d_out;

    void *pf16, *ps16, *pcsr, *pP, *pbs;
    cudaGetSymbolAddress(&pf16, g_fused16);
    cudaGetSymbolAddress(&ps16, g_soc16);
    cudaGetSymbolAddress(&pcsr, g_csr);
    cudaGetSymbolAddress(&pP, g_P);
    cudaGetSymbolAddress(&pbs, g_bsum);

    __half* fused16[5];
    for (int k = 0; k <= 4; k++) fused16[k] = (__half*)pf16 + (size_t)k * NNF;
    __half* soc16[4];   // soc16[1..3]
    for (int l = 1; l <= 3; l++) soc16[l] = (__half*)ps16 + (size_t)(l - 1) * NUF;
    // soc gather source per layer k: k=0 is fused16[0] user rows.
    __half* socsrc[4];
    socsrc[0] = fused16[0];
    for (int l = 1; l < 4; l++) socsrc[l] = soc16[l];
    uint2* csr = (uint2*)pcsr;
    int* P = (int*)pP;
    int* bsum = (int*)pbs;

    // --- CSR build + fused16[0] ---
    zerobins_kernel<<<cdiv_ll(NBINS, 256), 256>>>(P);
    hist_kernel<<<H_I + H_S + H_B, 256>>>(
        P, ir, sr, (const float4*)uE, (const float4*)iE, (uint2*)fused16[0]);
    scan_blocks_kernel<<<SCAN_BLOCKS, 256>>>(P, bsum);
    addoff_kernel<<<cdiv_ll(NBINS, 256), 256>>>(P, bsum);
    scatter_kernel<<<H_I + H_S, 256>>>(P, csr, ir, ic, iv, sr, sc, sv);

    // --- fused SpMM + gate layers ---
    const int SPMM_BLOCKS = cdiv_ll((long long)N_NODE * 16, 256);  // 18750
    for (int k = 0; k < N_LAYER; k++) {
        spmm_gate_kernel<<<SPMM_BLOCKS, 256>>>(
            csr, P,
            fused16[k], socsrc[k],
            fused16[k + 1],
            (k < 3) ? soc16[k + 1] : (__half*)nullptr,
            Wg + (size_t)(k + 1) * 256, bg + (size_t)(k + 1) * 2);
    }

    final_kernel<<<cdiv_ll((long long)N_NODE * 32, 256), 256>>>(
        uE, iE, fused16[1], fused16[2], fused16[3], fused16[4],
        WL1, bL1, WL2, bL2, out);
}